// round 1
// baseline (speedup 1.0000x reference)
#include <cuda_runtime.h>
#include <math.h>

// Problem constants
#define BB 2
#define TT 2048
#define CD 768
#define HH 12
#define HDIM 64
#define DD2 32
#define FFD 3072
#define NROWS (BB*TT)          // 4096
static __device__ __constant__ float kEPS = 1e-5f;

// ---------------- scratch (device globals; no allocation allowed) -------------
__device__ float g_h [NROWS*CD];
__device__ float g_q [NROWS*CD];
__device__ float g_k [NROWS*CD];
__device__ float g_v [NROWS*CD];
__device__ float g_y [NROWS*CD];
__device__ float g_x2[NROWS*CD];
__device__ float g_ff[NROWS*FFD];

// ---------------- RMSNorm ----------------
__global__ __launch_bounds__(256) void rmsnorm_kernel(const float* __restrict__ x,
                                                      const float* __restrict__ g,
                                                      float* __restrict__ out) {
    int row = blockIdx.x;
    const float* xr = x + (size_t)row * CD;
    float ss = 0.f;
    for (int i = threadIdx.x; i < CD; i += 256) { float v = xr[i]; ss += v * v; }
    #pragma unroll
    for (int o = 16; o; o >>= 1) ss += __shfl_xor_sync(0xffffffffu, ss, o);
    __shared__ float red[8];
    if ((threadIdx.x & 31) == 0) red[threadIdx.x >> 5] = ss;
    __syncthreads();
    float tot = 0.f;
    #pragma unroll
    for (int i = 0; i < 8; i++) tot += red[i];
    float rinv = rsqrtf(tot / (float)CD + kEPS);
    float* orow = out + (size_t)row * CD;
    for (int i = threadIdx.x; i < CD; i += 256) orow[i] = g[i] * xr[i] * rinv;
}

// ---------------- RoPE (applied in-place to q and k) ----------------
__global__ __launch_bounds__(256) void rope_kernel(float* __restrict__ q,
                                                   float* __restrict__ k,
                                                   const float* __restrict__ cs,
                                                   const float* __restrict__ sn) {
    int idx = blockIdx.x * 256 + threadIdx.x;          // over B*T*H*D2
    if (idx >= BB * TT * HH * DD2) return;
    int d  = idx % DD2;
    int h  = (idx / DD2) % HH;
    int bt = idx / (DD2 * HH);
    int t  = bt % TT;
    float c = cs[t * DD2 + d];
    float s = sn[t * DD2 + d];
    size_t base = (size_t)bt * CD + h * HDIM;
    float q1 = q[base + d], q2 = q[base + DD2 + d];
    q[base + d]       =  q1 * c + q2 * s;
    q[base + DD2 + d] = -q1 * s + q2 * c;
    float k1 = k[base + d], k2 = k[base + DD2 + d];
    k[base + d]       =  k1 * c + k2 * s;
    k[base + DD2 + d] = -k1 * s + k2 * c;
}

// ---------------- SGEMM 128x128x8, 8x8 microtiles ----------------
// EPI: 0 = plain, 1 = out = acc + R, 2 = out = relu(acc)^2
template <int EPI>
__global__ __launch_bounds__(256) void sgemm_kernel(const float* __restrict__ A,
                                                    const float* __restrict__ W,
                                                    const float* __restrict__ R,
                                                    float* __restrict__ Out,
                                                    int M, int N, int K) {
    __shared__ float As[8][128];
    __shared__ float Bs[8][128];
    int tid = threadIdx.x;
    int bm = blockIdx.y * 128, bn = blockIdx.x * 128;
    int arow  = tid >> 1, acol4 = (tid & 1) * 4;
    int brow  = tid >> 5, bcol4 = (tid & 31) * 4;
    int ty = tid >> 4, tx = tid & 15;
    float acc[8][8];
    #pragma unroll
    for (int i = 0; i < 8; i++)
        #pragma unroll
        for (int j = 0; j < 8; j++) acc[i][j] = 0.f;

    for (int k0 = 0; k0 < K; k0 += 8) {
        float4 av = *(const float4*)(A + (size_t)(bm + arow) * K + k0 + acol4);
        float4 bv = *(const float4*)(W + (size_t)(k0 + brow) * N + bn + bcol4);
        As[acol4 + 0][arow] = av.x;
        As[acol4 + 1][arow] = av.y;
        As[acol4 + 2][arow] = av.z;
        As[acol4 + 3][arow] = av.w;
        *(float4*)&Bs[brow][bcol4] = bv;
        __syncthreads();
        #pragma unroll
        for (int kk = 0; kk < 8; kk++) {
            float4 a0 = *(const float4*)&As[kk][ty * 8];
            float4 a1 = *(const float4*)&As[kk][ty * 8 + 4];
            float4 b0 = *(const float4*)&Bs[kk][tx * 8];
            float4 b1 = *(const float4*)&Bs[kk][tx * 8 + 4];
            float a[8] = {a0.x, a0.y, a0.z, a0.w, a1.x, a1.y, a1.z, a1.w};
            float b[8] = {b0.x, b0.y, b0.z, b0.w, b1.x, b1.y, b1.z, b1.w};
            #pragma unroll
            for (int i = 0; i < 8; i++)
                #pragma unroll
                for (int j = 0; j < 8; j++) acc[i][j] += a[i] * b[j];
        }
        __syncthreads();
    }

    #pragma unroll
    for (int i = 0; i < 8; i++) {
        size_t r = (size_t)(bm + ty * 8 + i);
        #pragma unroll
        for (int j = 0; j < 8; j++) {
            int c = bn + tx * 8 + j;
            float vv = acc[i][j];
            if (EPI == 1) vv += R[r * N + c];
            if (EPI == 2) { vv = fmaxf(vv, 0.f); vv = vv * vv; }
            Out[r * N + c] = vv;
        }
    }
}

// ---------------- Causal Flash Attention ----------------
// Tiles: 64 q-rows x 64 keys, HD=64. Block = 256 threads as 16x16 of 4x4 microtiles.
#define ATTN_SMEM (4 * 64 * 65 * 4)
__global__ __launch_bounds__(256) void attn_kernel(const float* __restrict__ q,
                                                   const float* __restrict__ k,
                                                   const float* __restrict__ v,
                                                   float* __restrict__ y) {
    extern __shared__ float smem[];
    float (*sQ)[65] = (float(*)[65])(smem);
    float (*sK)[65] = (float(*)[65])(smem + 64 * 65);
    float (*sV)[65] = (float(*)[65])(smem + 2 * 64 * 65);
    float (*sP)[65] = (float(*)[65])(smem + 3 * 64 * 65);

    int qt = blockIdx.x, h = blockIdx.y, b = blockIdx.z;
    int tid = threadIdx.x;
    int tr = tid >> 4, tc = tid & 15;          // 16x16 grid of threads
    int qs = qt * 64;
    size_t bh = (size_t)b * TT * CD + (size_t)h * HDIM;  // add t*CD for row t

    // Load Q tile (64 x 64)
    for (int i = tid; i < 64 * 16; i += 256) {
        int r = i >> 4, c4 = (i & 15) * 4;
        float4 vq = *(const float4*)(q + bh + (size_t)(qs + r) * CD + c4);
        sQ[r][c4] = vq.x; sQ[r][c4 + 1] = vq.y; sQ[r][c4 + 2] = vq.z; sQ[r][c4 + 3] = vq.w;
    }

    float m[4], l[4], acc[4][4];
    #pragma unroll
    for (int i = 0; i < 4; i++) {
        m[i] = -1e30f; l[i] = 0.f;
        #pragma unroll
        for (int j = 0; j < 4; j++) acc[i][j] = 0.f;
    }

    const float scale = 0.125f;  // 1/sqrt(64)

    for (int kt = 0; kt <= qt; kt++) {
        int ks = kt * 64;
        __syncthreads();  // prior PV reads of sP/sV done before overwrite
        for (int i = tid; i < 64 * 16; i += 256) {
            int r = i >> 4, c4 = (i & 15) * 4;
            float4 vk = *(const float4*)(k + bh + (size_t)(ks + r) * CD + c4);
            sK[r][c4] = vk.x; sK[r][c4 + 1] = vk.y; sK[r][c4 + 2] = vk.z; sK[r][c4 + 3] = vk.w;
            float4 vv = *(const float4*)(v + bh + (size_t)(ks + r) * CD + c4);
            sV[r][c4] = vv.x; sV[r][c4 + 1] = vv.y; sV[r][c4 + 2] = vv.z; sV[r][c4 + 3] = vv.w;
        }
        __syncthreads();

        // S = Q K^T  (4x4 per thread)
        float s[4][4];
        #pragma unroll
        for (int i = 0; i < 4; i++)
            #pragma unroll
            for (int j = 0; j < 4; j++) s[i][j] = 0.f;
        #pragma unroll 8
        for (int kk = 0; kk < 64; kk++) {
            float qr[4], kr[4];
            #pragma unroll
            for (int i = 0; i < 4; i++) qr[i] = sQ[tr * 4 + i][kk];
            #pragma unroll
            for (int j = 0; j < 4; j++) kr[j] = sK[tc * 4 + j][kk];
            #pragma unroll
            for (int i = 0; i < 4; i++)
                #pragma unroll
                for (int j = 0; j < 4; j++) s[i][j] += qr[i] * kr[j];
        }

        // scale + causal mask (only diagonal tile needs it)
        #pragma unroll
        for (int i = 0; i < 4; i++)
            #pragma unroll
            for (int j = 0; j < 4; j++) {
                s[i][j] *= scale;
                if (kt == qt && (tr * 4 + i) < (tc * 4 + j)) s[i][j] = -1e30f;
            }

        // online softmax
        float p[4][4];
        #pragma unroll
        for (int i = 0; i < 4; i++) {
            float rowm = s[i][0];
            #pragma unroll
            for (int j = 1; j < 4; j++) rowm = fmaxf(rowm, s[i][j]);
            #pragma unroll
            for (int o = 1; o < 16; o <<= 1)
                rowm = fmaxf(rowm, __shfl_xor_sync(0xffffffffu, rowm, o, 16));
            float mnew = fmaxf(m[i], rowm);
            float alpha = __expf(m[i] - mnew);
            float rs = 0.f;
            #pragma unroll
            for (int j = 0; j < 4; j++) { p[i][j] = __expf(s[i][j] - mnew); rs += p[i][j]; }
            #pragma unroll
            for (int o = 1; o < 16; o <<= 1)
                rs += __shfl_xor_sync(0xffffffffu, rs, o, 16);
            l[i] = l[i] * alpha + rs;
            #pragma unroll
            for (int j = 0; j < 4; j++) acc[i][j] *= alpha;
            m[i] = mnew;
        }

        // write P
        #pragma unroll
        for (int i = 0; i < 4; i++)
            #pragma unroll
            for (int j = 0; j < 4; j++) sP[tr * 4 + i][tc * 4 + j] = p[i][j];
        __syncthreads();

        // O += P V
        #pragma unroll 8
        for (int c = 0; c < 64; c++) {
            float pv[4], vv[4];
            #pragma unroll
            for (int i = 0; i < 4; i++) pv[i] = sP[tr * 4 + i][c];
            #pragma unroll
            for (int j = 0; j < 4; j++) vv[j] = sV[c][tc * 4 + j];
            #pragma unroll
            for (int i = 0; i < 4; i++)
                #pragma unroll
                for (int j = 0; j < 4; j++) acc[i][j] += pv[i] * vv[j];
        }
    }

    // write out O = acc / l
    #pragma unroll
    for (int i = 0; i < 4; i++) {
        float inv = 1.f / l[i];
        #pragma unroll
        for (int j = 0; j < 4; j++)
            y[bh + (size_t)(qs + tr * 4 + i) * CD + tc * 4 + j] = acc[i][j] * inv;
    }
}

// ---------------- launch ----------------
extern "C" void kernel_launch(void* const* d_in, const int* in_sizes, int n_in,
                              void* d_out, int out_size) {
    const float* x   = (const float*)d_in[0];
    const float* cs  = (const float*)d_in[1];
    const float* sn  = (const float*)d_in[2];
    const float* wq  = (const float*)d_in[3];
    const float* wk  = (const float*)d_in[4];
    const float* wv  = (const float*)d_in[5];
    const float* wo  = (const float*)d_in[6];
    const float* wfc = (const float*)d_in[7];
    const float* wpr = (const float*)d_in[8];
    const float* g1  = (const float*)d_in[9];
    const float* g2  = (const float*)d_in[10];
    float* out = (float*)d_out;

    float *h, *q, *k, *v, *y, *x2, *ff;
    cudaGetSymbolAddress((void**)&h,  g_h);
    cudaGetSymbolAddress((void**)&q,  g_q);
    cudaGetSymbolAddress((void**)&k,  g_k);
    cudaGetSymbolAddress((void**)&v,  g_v);
    cudaGetSymbolAddress((void**)&y,  g_y);
    cudaGetSymbolAddress((void**)&x2, g_x2);
    cudaGetSymbolAddress((void**)&ff, g_ff);

    cudaFuncSetAttribute((const void*)attn_kernel,
                         cudaFuncAttributeMaxDynamicSharedMemorySize, ATTN_SMEM);

    // 1. h = rmsnorm(x, g1)
    rmsnorm_kernel<<<NROWS, 256>>>(x, g1, h);

    // 2. q,k,v = h @ {wq,wk,wv}
    dim3 gQKV(CD / 128, NROWS / 128);
    sgemm_kernel<0><<<gQKV, 256>>>(h, wq, nullptr, q, NROWS, CD, CD);
    sgemm_kernel<0><<<gQKV, 256>>>(h, wk, nullptr, k, NROWS, CD, CD);
    sgemm_kernel<0><<<gQKV, 256>>>(h, wv, nullptr, v, NROWS, CD, CD);

    // 3. RoPE in-place on q,k
    int nrope = BB * TT * HH * DD2;
    rope_kernel<<<(nrope + 255) / 256, 256>>>(q, k, cs, sn);

    // 4. attention -> y
    attn_kernel<<<dim3(TT / 64, HH, BB), 256, ATTN_SMEM>>>(q, k, v, y);

    // 5. x2 = x + y @ wo
    sgemm_kernel<1><<<gQKV, 256>>>(y, wo, x, x2, NROWS, CD, CD);

    // 6. h = rmsnorm(x2, g2)
    rmsnorm_kernel<<<NROWS, 256>>>(x2, g2, h);

    // 7. ff = relu(h @ wfc)^2
    dim3 gFC(FFD / 128, NROWS / 128);
    sgemm_kernel<2><<<gFC, 256>>>(h, wfc, nullptr, ff, NROWS, FFD, CD);

    // 8. out = x2 + ff @ wpr
    sgemm_kernel<1><<<gQKV, 256>>>(ff, wpr, x2, out, NROWS, CD, FFD);
}

// round 3
// speedup vs baseline: 2.0171x; 2.0171x over previous
#include <cuda_runtime.h>
#include <math.h>
#include <stdint.h>

// Problem constants
#define BB 2
#define TT 2048
#define CD 768
#define HH 12
#define HDIM 64
#define DD2 32
#define FFD 3072
#define NROWS (BB*TT)          // 4096
static __device__ __constant__ float kEPS = 1e-5f;

// ---------------- scratch ----------------
__device__ float g_h [NROWS*CD];
__device__ float g_q [NROWS*CD];
__device__ float g_k [NROWS*CD];
__device__ float g_v [NROWS*CD];
__device__ float g_y [NROWS*CD];
__device__ float g_x2[NROWS*CD];
__device__ float g_ff[NROWS*FFD];

// ---------------- mma.sync tf32 helpers ----------------
__device__ __forceinline__ uint32_t f2tf32(float f) {
    uint32_t r;
    asm("cvt.rna.tf32.f32 %0, %1;" : "=r"(r) : "f"(f));
    return r;
}
__device__ __forceinline__ void mma_tf32(float* c, const uint32_t* a, const uint32_t* b) {
    asm volatile(
        "mma.sync.aligned.m16n8k8.row.col.f32.tf32.tf32.f32 "
        "{%0,%1,%2,%3}, {%4,%5,%6,%7}, {%8,%9}, {%0,%1,%2,%3};"
        : "+f"(c[0]), "+f"(c[1]), "+f"(c[2]), "+f"(c[3])
        : "r"(a[0]), "r"(a[1]), "r"(a[2]), "r"(a[3]), "r"(b[0]), "r"(b[1]));
}

// SMEM geometry: K-major chunks of 32, padded stride 136 floats (conflict-free frags)
#define SSTRIDE 136
#define BUF_FLOATS (32 * SSTRIDE)            // one operand tile, 4352 floats
#define GEMM_SMEM (2 * 2 * BUF_FLOATS * 4)   // double-buffered A+B = 69632 B

// ============ GEMM core (device inline): CTA 128x128, 256 thr, warp tile 32x64 ============
// A [M,K] row-major, W [K,N] row-major. acc produced in registers c[2][8][4].
// Thread map: warp w = tid>>5; wy = w>>1 (4 row groups of 32), wx = w&1 (2 col groups of 64).
// gid = lane>>2, tig = lane&3.
struct GemmAcc { float c[2][8][4]; };

__device__ __forceinline__ void gemm_mainloop(const float* __restrict__ A,
                                              const float* __restrict__ W,
                                              int M, int N, int K,
                                              int bm, int bn, float* sm,
                                              GemmAcc& G) {
    const int tid = threadIdx.x;
    const int warp = tid >> 5, lane = tid & 31;
    const int wy = warp >> 1, wx = warp & 1;
    const int gid = lane >> 2, tig = lane & 3;

    #pragma unroll
    for (int i = 0; i < 2; i++)
        #pragma unroll
        for (int j = 0; j < 8; j++)
            #pragma unroll
            for (int t = 0; t < 4; t++) G.c[i][j][t] = 0.f;

    const int NC = K >> 5;
    // staging registers
    float4 ra[4], rb[4];
    const int ar = tid >> 1, ak4 = (tid & 1) * 4;       // A: row, k-offset
    const int bk = tid >> 3, bn4 = (tid & 7) * 4;       // B: k-row, n-offset

    // prologue: load chunk 0
    #pragma unroll
    for (int p = 0; p < 4; p++) {
        ra[p] = *(const float4*)(A + (size_t)(bm + ar) * K + ak4 + p * 8);
        rb[p] = *(const float4*)(W + (size_t)bk * N + bn + bn4 + p * 32);
    }
    {
        float* As = sm;
        float* Bs = sm + BUF_FLOATS;
        #pragma unroll
        for (int p = 0; p < 4; p++) {
            const float* a = &ra[p].x;
            #pragma unroll
            for (int jj = 0; jj < 4; jj++)
                ((uint32_t*)As)[(ak4 + p * 8 + jj) * SSTRIDE + ar] = f2tf32(a[jj]);
            uint32_t* d = (uint32_t*)Bs + bk * SSTRIDE + bn4 + p * 32;
            d[0] = f2tf32(rb[p].x); d[1] = f2tf32(rb[p].y);
            d[2] = f2tf32(rb[p].z); d[3] = f2tf32(rb[p].w);
        }
    }
    __syncthreads();

    for (int c = 0; c < NC; c++) {
        // prefetch next chunk (global -> regs)
        if (c + 1 < NC) {
            #pragma unroll
            for (int p = 0; p < 4; p++) {
                ra[p] = *(const float4*)(A + (size_t)(bm + ar) * K + (c + 1) * 32 + ak4 + p * 8);
                rb[p] = *(const float4*)(W + (size_t)((c + 1) * 32 + bk) * N + bn + bn4 + p * 32);
            }
        }
        // compute on current buffer
        {
            const uint32_t* uA = (const uint32_t*)(sm + (c & 1) * 2 * BUF_FLOATS);
            const uint32_t* uB = uA + BUF_FLOATS;
            #pragma unroll
            for (int ks = 0; ks < 4; ks++) {
                const int kb = ks * 8;
                uint32_t af[2][4];
                #pragma unroll
                for (int i = 0; i < 2; i++) {
                    const int rb_ = wy * 32 + i * 16;
                    af[i][0] = uA[(kb + tig) * SSTRIDE + rb_ + gid];
                    af[i][1] = uA[(kb + tig) * SSTRIDE + rb_ + gid + 8];
                    af[i][2] = uA[(kb + tig + 4) * SSTRIDE + rb_ + gid];
                    af[i][3] = uA[(kb + tig + 4) * SSTRIDE + rb_ + gid + 8];
                }
                uint32_t bf[8][2];
                #pragma unroll
                for (int j = 0; j < 8; j++) {
                    const int cb = wx * 64 + j * 8;
                    bf[j][0] = uB[(kb + tig) * SSTRIDE + cb + gid];
                    bf[j][1] = uB[(kb + tig + 4) * SSTRIDE + cb + gid];
                }
                #pragma unroll
                for (int i = 0; i < 2; i++)
                    #pragma unroll
                    for (int j = 0; j < 8; j++) mma_tf32(G.c[i][j], af[i], bf[j]);
            }
        }
        // store next chunk into the other buffer
        if (c + 1 < NC) {
            float* As = sm + ((c + 1) & 1) * 2 * BUF_FLOATS;
            float* Bs = As + BUF_FLOATS;
            #pragma unroll
            for (int p = 0; p < 4; p++) {
                const float* a = &ra[p].x;
                #pragma unroll
                for (int jj = 0; jj < 4; jj++)
                    ((uint32_t*)As)[(ak4 + p * 8 + jj) * SSTRIDE + ar] = f2tf32(a[jj]);
                uint32_t* d = (uint32_t*)Bs + bk * SSTRIDE + bn4 + p * 32;
                d[0] = f2tf32(rb[p].x); d[1] = f2tf32(rb[p].y);
                d[2] = f2tf32(rb[p].z); d[3] = f2tf32(rb[p].w);
            }
        }
        __syncthreads();
    }
}

// ============ generic GEMM kernel: EPI 0 plain, 1 +R, 2 relu^2 ============
template <int EPI>
__global__ __launch_bounds__(256) void gemm_mma(const float* __restrict__ A,
                                                const float* __restrict__ W,
                                                const float* __restrict__ R,
                                                float* __restrict__ Out,
                                                int M, int N, int K) {
    extern __shared__ float sm[];
    const int bm = blockIdx.y * 128, bn = blockIdx.x * 128;
    GemmAcc G;
    gemm_mainloop(A, W, M, N, K, bm, bn, sm, G);

    const int tid = threadIdx.x;
    const int warp = tid >> 5, lane = tid & 31;
    const int wy = warp >> 1, wx = warp & 1;
    const int gid = lane >> 2, tig = lane & 3;

    #pragma unroll
    for (int i = 0; i < 2; i++) {
        const int r0 = bm + wy * 32 + i * 16 + gid;
        const int r1 = r0 + 8;
        #pragma unroll
        for (int j = 0; j < 8; j++) {
            const int cc = bn + wx * 64 + j * 8 + 2 * tig;
            float v0 = G.c[i][j][0], v1 = G.c[i][j][1];
            float v2 = G.c[i][j][2], v3 = G.c[i][j][3];
            if (EPI == 1) {
                float2 t0 = *(const float2*)(R + (size_t)r0 * N + cc);
                float2 t1 = *(const float2*)(R + (size_t)r1 * N + cc);
                v0 += t0.x; v1 += t0.y; v2 += t1.x; v3 += t1.y;
            }
            if (EPI == 2) {
                v0 = fmaxf(v0, 0.f); v0 *= v0;
                v1 = fmaxf(v1, 0.f); v1 *= v1;
                v2 = fmaxf(v2, 0.f); v2 *= v2;
                v3 = fmaxf(v3, 0.f); v3 *= v3;
            }
            *(float2*)(Out + (size_t)r0 * N + cc) = make_float2(v0, v1);
            *(float2*)(Out + (size_t)r1 * N + cc) = make_float2(v2, v3);
        }
    }
}

// ============ fused QKV GEMM with RoPE epilogue on q,k ============
// grid: x = 18 (mat = bx/6, column block = bx%6), y = 32 (row blocks)
__global__ __launch_bounds__(256) void qkv_gemm(const float* __restrict__ A,
                                                const float* __restrict__ wq,
                                                const float* __restrict__ wk,
                                                const float* __restrict__ wv,
                                                const float* __restrict__ cs,
                                                const float* __restrict__ sn,
                                                float* __restrict__ q,
                                                float* __restrict__ k,
                                                float* __restrict__ v) {
    extern __shared__ float sm[];
    const int mat = blockIdx.x / 6;
    const int bn = (blockIdx.x % 6) * 128;
    const int bm = blockIdx.y * 128;
    const float* W = (mat == 0) ? wq : (mat == 1) ? wk : wv;
    float* Out = (mat == 0) ? q : (mat == 1) ? k : v;

    GemmAcc G;
    gemm_mainloop(A, W, NROWS, CD, CD, bm, bn, sm, G);

    const int tid = threadIdx.x;
    const int warp = tid >> 5, lane = tid & 31;
    const int wy = warp >> 1, wx = warp & 1;
    const int gid = lane >> 2, tig = lane & 3;

    if (mat == 2) {  // v: plain store
        #pragma unroll
        for (int i = 0; i < 2; i++) {
            const int r0 = bm + wy * 32 + i * 16 + gid;
            const int r1 = r0 + 8;
            #pragma unroll
            for (int j = 0; j < 8; j++) {
                const int cc = bn + wx * 64 + j * 8 + 2 * tig;
                *(float2*)(Out + (size_t)r0 * CD + cc) = make_float2(G.c[i][j][0], G.c[i][j][1]);
                *(float2*)(Out + (size_t)r1 * CD + cc) = make_float2(G.c[i][j][2], G.c[i][j][3]);
            }
        }
    } else {  // q,k: RoPE. Pair (d, d+32) = frags (j, j+4), d = j*8 + 2*tig < 32.
        #pragma unroll
        for (int i = 0; i < 2; i++) {
            const int r0 = bm + wy * 32 + i * 16 + gid;
            const int r1 = r0 + 8;
            const int t0 = r0 & (TT - 1), t1 = r1 & (TT - 1);
            #pragma unroll
            for (int j = 0; j < 4; j++) {
                const int d = j * 8 + 2 * tig;
                const int cc = bn + wx * 64 + j * 8 + 2 * tig;
                float2 c0 = *(const float2*)(cs + t0 * DD2 + d);
                float2 s0 = *(const float2*)(sn + t0 * DD2 + d);
                float2 c1 = *(const float2*)(cs + t1 * DD2 + d);
                float2 s1 = *(const float2*)(sn + t1 * DD2 + d);
                // row r0
                float x1a = G.c[i][j][0], x1b = G.c[i][j][1];
                float x2a = G.c[i][j + 4][0], x2b = G.c[i][j + 4][1];
                *(float2*)(Out + (size_t)r0 * CD + cc) =
                    make_float2(x1a * c0.x + x2a * s0.x, x1b * c0.y + x2b * s0.y);
                *(float2*)(Out + (size_t)r0 * CD + cc + 32) =
                    make_float2(-x1a * s0.x + x2a * c0.x, -x1b * s0.y + x2b * c0.y);
                // row r1
                float y1a = G.c[i][j][2], y1b = G.c[i][j][3];
                float y2a = G.c[i][j + 4][2], y2b = G.c[i][j + 4][3];
                *(float2*)(Out + (size_t)r1 * CD + cc) =
                    make_float2(y1a * c1.x + y2a * s1.x, y1b * c1.y + y2b * s1.y);
                *(float2*)(Out + (size_t)r1 * CD + cc + 32) =
                    make_float2(-y1a * s1.x + y2a * c1.x, -y1b * s1.y + y2b * c1.y);
            }
        }
    }
}

// ---------------- RMSNorm ----------------
__global__ __launch_bounds__(256) void rmsnorm_kernel(const float* __restrict__ x,
                                                      const float* __restrict__ g,
                                                      float* __restrict__ out) {
    int row = blockIdx.x;
    const float* xr = x + (size_t)row * CD;
    float ss = 0.f;
    for (int i = threadIdx.x; i < CD; i += 256) { float v = xr[i]; ss += v * v; }
    #pragma unroll
    for (int o = 16; o; o >>= 1) ss += __shfl_xor_sync(0xffffffffu, ss, o);
    __shared__ float red[8];
    if ((threadIdx.x & 31) == 0) red[threadIdx.x >> 5] = ss;
    __syncthreads();
    float tot = 0.f;
    #pragma unroll
    for (int i = 0; i < 8; i++) tot += red[i];
    float rinv = rsqrtf(tot / (float)CD + kEPS);
    float* orow = out + (size_t)row * CD;
    for (int i = threadIdx.x; i < CD; i += 256) orow[i] = g[i] * xr[i] * rinv;
}

// ---------------- Causal Flash Attention (SIMT fp32) ----------------
#define ATTN_SMEM (4 * 64 * 65 * 4)
__global__ __launch_bounds__(256) void attn_kernel(const float* __restrict__ q,
                                                   const float* __restrict__ k,
                                                   const float* __restrict__ v,
                                                   float* __restrict__ y) {
    extern __shared__ float asmem[];
    float (*sQ)[65] = (float(*)[65])(asmem);
    float (*sK)[65] = (float(*)[65])(asmem + 64 * 65);
    float (*sV)[65] = (float(*)[65])(asmem + 2 * 64 * 65);
    float (*sP)[65] = (float(*)[65])(asmem + 3 * 64 * 65);

    int qt = blockIdx.x, h = blockIdx.y, b = blockIdx.z;
    int tid = threadIdx.x;
    int tr = tid >> 4, tc = tid & 15;
    int qs = qt * 64;
    size_t bh = (size_t)b * TT * CD + (size_t)h * HDIM;

    for (int i = tid; i < 64 * 16; i += 256) {
        int r = i >> 4, c4 = (i & 15) * 4;
        float4 vq = *(const float4*)(q + bh + (size_t)(qs + r) * CD + c4);
        sQ[r][c4] = vq.x; sQ[r][c4 + 1] = vq.y; sQ[r][c4 + 2] = vq.z; sQ[r][c4 + 3] = vq.w;
    }

    float m[4], l[4], acc[4][4];
    #pragma unroll
    for (int i = 0; i < 4; i++) {
        m[i] = -1e30f; l[i] = 0.f;
        #pragma unroll
        for (int j = 0; j < 4; j++) acc[i][j] = 0.f;
    }
    const float scale = 0.125f;

    for (int kt = 0; kt <= qt; kt++) {
        int ks = kt * 64;
        __syncthreads();
        for (int i = tid; i < 64 * 16; i += 256) {
            int r = i >> 4, c4 = (i & 15) * 4;
            float4 vk = *(const float4*)(k + bh + (size_t)(ks + r) * CD + c4);
            sK[r][c4] = vk.x; sK[r][c4 + 1] = vk.y; sK[r][c4 + 2] = vk.z; sK[r][c4 + 3] = vk.w;
            float4 vv = *(const float4*)(v + bh + (size_t)(ks + r) * CD + c4);
            sV[r][c4] = vv.x; sV[r][c4 + 1] = vv.y; sV[r][c4 + 2] = vv.z; sV[r][c4 + 3] = vv.w;
        }
        __syncthreads();

        float s[4][4];
        #pragma unroll
        for (int i = 0; i < 4; i++)
            #pragma unroll
            for (int j = 0; j < 4; j++) s[i][j] = 0.f;
        #pragma unroll 8
        for (int kk = 0; kk < 64; kk++) {
            float qr[4], kr[4];
            #pragma unroll
            for (int i = 0; i < 4; i++) qr[i] = sQ[tr * 4 + i][kk];
            #pragma unroll
            for (int j = 0; j < 4; j++) kr[j] = sK[tc * 4 + j][kk];
            #pragma unroll
            for (int i = 0; i < 4; i++)
                #pragma unroll
                for (int j = 0; j < 4; j++) s[i][j] += qr[i] * kr[j];
        }

        #pragma unroll
        for (int i = 0; i < 4; i++)
            #pragma unroll
            for (int j = 0; j < 4; j++) {
                s[i][j] *= scale;
                if (kt == qt && (tr * 4 + i) < (tc * 4 + j)) s[i][j] = -1e30f;
            }

        float p[4][4];
        #pragma unroll
        for (int i = 0; i < 4; i++) {
            float rowm = s[i][0];
            #pragma unroll
            for (int j = 1; j < 4; j++) rowm = fmaxf(rowm, s[i][j]);
            #pragma unroll
            for (int o = 1; o < 16; o <<= 1)
                rowm = fmaxf(rowm, __shfl_xor_sync(0xffffffffu, rowm, o, 16));
            float mnew = fmaxf(m[i], rowm);
            float alpha = __expf(m[i] - mnew);
            float rs = 0.f;
            #pragma unroll
            for (int j = 0; j < 4; j++) { p[i][j] = __expf(s[i][j] - mnew); rs += p[i][j]; }
            #pragma unroll
            for (int o = 1; o < 16; o <<= 1)
                rs += __shfl_xor_sync(0xffffffffu, rs, o, 16);
            l[i] = l[i] * alpha + rs;
            #pragma unroll
            for (int j = 0; j < 4; j++) acc[i][j] *= alpha;
            m[i] = mnew;
        }

        #pragma unroll
        for (int i = 0; i < 4; i++)
            #pragma unroll
            for (int j = 0; j < 4; j++) sP[tr * 4 + i][tc * 4 + j] = p[i][j];
        __syncthreads();

        #pragma unroll 8
        for (int c = 0; c < 64; c++) {
            float pv[4], vv[4];
            #pragma unroll
            for (int i = 0; i < 4; i++) pv[i] = sP[tr * 4 + i][c];
            #pragma unroll
            for (int j = 0; j < 4; j++) vv[j] = sV[c][tc * 4 + j];
            #pragma unroll
            for (int i = 0; i < 4; i++)
                #pragma unroll
                for (int j = 0; j < 4; j++) acc[i][j] += pv[i] * vv[j];
        }
    }

    #pragma unroll
    for (int i = 0; i < 4; i++) {
        float inv = 1.f / l[i];
        #pragma unroll
        for (int j = 0; j < 4; j++)
            y[bh + (size_t)(qs + tr * 4 + i) * CD + tc * 4 + j] = acc[i][j] * inv;
    }
}

// ---------------- launch ----------------
extern "C" void kernel_launch(void* const* d_in, const int* in_sizes, int n_in,
                              void* d_out, int out_size) {
    const float* x   = (const float*)d_in[0];
    const float* cs  = (const float*)d_in[1];
    const float* sn  = (const float*)d_in[2];
    const float* wq  = (const float*)d_in[3];
    const float* wk  = (const float*)d_in[4];
    const float* wv  = (const float*)d_in[5];
    const float* wo  = (const float*)d_in[6];
    const float* wfc = (const float*)d_in[7];
    const float* wpr = (const float*)d_in[8];
    const float* g1  = (const float*)d_in[9];
    const float* g2  = (const float*)d_in[10];
    float* out = (float*)d_out;

    float *h, *q, *k, *v, *y, *x2, *ff;
    cudaGetSymbolAddress((void**)&h,  g_h);
    cudaGetSymbolAddress((void**)&q,  g_q);
    cudaGetSymbolAddress((void**)&k,  g_k);
    cudaGetSymbolAddress((void**)&v,  g_v);
    cudaGetSymbolAddress((void**)&y,  g_y);
    cudaGetSymbolAddress((void**)&x2, g_x2);
    cudaGetSymbolAddress((void**)&ff, g_ff);

    cudaFuncSetAttribute((const void*)attn_kernel,
                         cudaFuncAttributeMaxDynamicSharedMemorySize, ATTN_SMEM);
    cudaFuncSetAttribute((const void*)qkv_gemm,
                         cudaFuncAttributeMaxDynamicSharedMemorySize, GEMM_SMEM);
    cudaFuncSetAttribute((const void*)gemm_mma<0>,
                         cudaFuncAttributeMaxDynamicSharedMemorySize, GEMM_SMEM);
    cudaFuncSetAttribute((const void*)gemm_mma<1>,
                         cudaFuncAttributeMaxDynamicSharedMemorySize, GEMM_SMEM);
    cudaFuncSetAttribute((const void*)gemm_mma<2>,
                         cudaFuncAttributeMaxDynamicSharedMemorySize, GEMM_SMEM);

    // 1. h = rmsnorm(x, g1)
    rmsnorm_kernel<<<NROWS, 256>>>(x, g1, h);

    // 2+3. q,k,v = h @ {wq,wk,wv}, RoPE fused on q,k
    qkv_gemm<<<dim3(18, 32), 256, GEMM_SMEM>>>(h, wq, wk, wv, cs, sn, q, k, v);

    // 4. attention -> y
    attn_kernel<<<dim3(TT / 64, HH, BB), 256, ATTN_SMEM>>>(q, k, v, y);

    // 5. x2 = x + y @ wo
    dim3 gCC(CD / 128, NROWS / 128);
    gemm_mma<1><<<gCC, 256, GEMM_SMEM>>>(y, wo, x, x2, NROWS, CD, CD);

    // 6. h = rmsnorm(x2, g2)
    rmsnorm_kernel<<<NROWS, 256>>>(x2, g2, h);

    // 7. ff = relu(h @ wfc)^2
    dim3 gFC(FFD / 128, NROWS / 128);
    gemm_mma<2><<<gFC, 256, GEMM_SMEM>>>(h, wfc, nullptr, ff, NROWS, FFD, CD);

    // 8. out = x2 + ff @ wpr
    gemm_mma<1><<<gCC, 256, GEMM_SMEM>>>(ff, wpr, x2, out, NROWS, CD, FFD);
}

// round 4
// speedup vs baseline: 3.1102x; 1.5419x over previous
#include <cuda_runtime.h>
#include <math.h>
#include <stdint.h>

// Problem constants
#define BB 2
#define TT 2048
#define CD 768
#define HH 12
#define HDIM 64
#define DD2 32
#define FFD 3072
#define NROWS (BB*TT)          // 4096
static __device__ __constant__ float kEPS = 1e-5f;

// ---------------- scratch ----------------
__device__ float g_h [NROWS*CD];
__device__ float g_q [NROWS*CD];
__device__ float g_k [NROWS*CD];
__device__ float g_v [NROWS*CD];
__device__ float g_y [NROWS*CD];
__device__ float g_x2[NROWS*CD];
__device__ float g_ff[NROWS*FFD];

// ---------------- mma.sync tf32 helpers ----------------
__device__ __forceinline__ uint32_t f2tf32(float f) {
    uint32_t r;
    asm("cvt.rna.tf32.f32 %0, %1;" : "=r"(r) : "f"(f));
    return r;
}
__device__ __forceinline__ void mma_tf32(float* c, const uint32_t* a, const uint32_t* b) {
    asm volatile(
        "mma.sync.aligned.m16n8k8.row.col.f32.tf32.tf32.f32 "
        "{%0,%1,%2,%3}, {%4,%5,%6,%7}, {%8,%9}, {%0,%1,%2,%3};"
        : "+f"(c[0]), "+f"(c[1]), "+f"(c[2]), "+f"(c[3])
        : "r"(a[0]), "r"(a[1]), "r"(a[2]), "r"(a[3]), "r"(b[0]), "r"(b[1]));
}

// SMEM geometry: K-major chunks of 32, padded stride 136 floats
#define SSTRIDE 136
#define BUF_FLOATS (32 * SSTRIDE)
#define GEMM_SMEM (2 * 2 * BUF_FLOATS * 4)   // 69632 B

// ============ GEMM core: CTA 128x128, 256 thr, warp tile 32x64 ============
struct GemmAcc { float c[2][8][4]; };

__device__ __forceinline__ void gemm_mainloop(const float* __restrict__ A,
                                              const float* __restrict__ W,
                                              int M, int N, int K,
                                              int bm, int bn, float* sm,
                                              GemmAcc& G) {
    const int tid = threadIdx.x;
    const int warp = tid >> 5, lane = tid & 31;
    const int wy = warp >> 1, wx = warp & 1;
    const int gid = lane >> 2, tig = lane & 3;

    #pragma unroll
    for (int i = 0; i < 2; i++)
        #pragma unroll
        for (int j = 0; j < 8; j++)
            #pragma unroll
            for (int t = 0; t < 4; t++) G.c[i][j][t] = 0.f;

    const int NC = K >> 5;
    float4 ra[4], rb[4];
    const int ar = tid >> 1, ak4 = (tid & 1) * 4;
    const int bk = tid >> 3, bn4 = (tid & 7) * 4;

    #pragma unroll
    for (int p = 0; p < 4; p++) {
        ra[p] = *(const float4*)(A + (size_t)(bm + ar) * K + ak4 + p * 8);
        rb[p] = *(const float4*)(W + (size_t)bk * N + bn + bn4 + p * 32);
    }
    {
        float* As = sm;
        float* Bs = sm + BUF_FLOATS;
        #pragma unroll
        for (int p = 0; p < 4; p++) {
            const float* a = &ra[p].x;
            #pragma unroll
            for (int jj = 0; jj < 4; jj++)
                ((uint32_t*)As)[(ak4 + p * 8 + jj) * SSTRIDE + ar] = f2tf32(a[jj]);
            uint32_t* d = (uint32_t*)Bs + bk * SSTRIDE + bn4 + p * 32;
            d[0] = f2tf32(rb[p].x); d[1] = f2tf32(rb[p].y);
            d[2] = f2tf32(rb[p].z); d[3] = f2tf32(rb[p].w);
        }
    }
    __syncthreads();

    for (int c = 0; c < NC; c++) {
        if (c + 1 < NC) {
            #pragma unroll
            for (int p = 0; p < 4; p++) {
                ra[p] = *(const float4*)(A + (size_t)(bm + ar) * K + (c + 1) * 32 + ak4 + p * 8);
                rb[p] = *(const float4*)(W + (size_t)((c + 1) * 32 + bk) * N + bn + bn4 + p * 32);
            }
        }
        {
            const uint32_t* uA = (const uint32_t*)(sm + (c & 1) * 2 * BUF_FLOATS);
            const uint32_t* uB = uA + BUF_FLOATS;
            #pragma unroll
            for (int ks = 0; ks < 4; ks++) {
                const int kb = ks * 8;
                uint32_t af[2][4];
                #pragma unroll
                for (int i = 0; i < 2; i++) {
                    const int rb_ = wy * 32 + i * 16;
                    af[i][0] = uA[(kb + tig) * SSTRIDE + rb_ + gid];
                    af[i][1] = uA[(kb + tig) * SSTRIDE + rb_ + gid + 8];
                    af[i][2] = uA[(kb + tig + 4) * SSTRIDE + rb_ + gid];
                    af[i][3] = uA[(kb + tig + 4) * SSTRIDE + rb_ + gid + 8];
                }
                uint32_t bf[8][2];
                #pragma unroll
                for (int j = 0; j < 8; j++) {
                    const int cb = wx * 64 + j * 8;
                    bf[j][0] = uB[(kb + tig) * SSTRIDE + cb + gid];
                    bf[j][1] = uB[(kb + tig + 4) * SSTRIDE + cb + gid];
                }
                #pragma unroll
                for (int i = 0; i < 2; i++)
                    #pragma unroll
                    for (int j = 0; j < 8; j++) mma_tf32(G.c[i][j], af[i], bf[j]);
            }
        }
        if (c + 1 < NC) {
            float* As = sm + ((c + 1) & 1) * 2 * BUF_FLOATS;
            float* Bs = As + BUF_FLOATS;
            #pragma unroll
            for (int p = 0; p < 4; p++) {
                const float* a = &ra[p].x;
                #pragma unroll
                for (int jj = 0; jj < 4; jj++)
                    ((uint32_t*)As)[(ak4 + p * 8 + jj) * SSTRIDE + ar] = f2tf32(a[jj]);
                uint32_t* d = (uint32_t*)Bs + bk * SSTRIDE + bn4 + p * 32;
                d[0] = f2tf32(rb[p].x); d[1] = f2tf32(rb[p].y);
                d[2] = f2tf32(rb[p].z); d[3] = f2tf32(rb[p].w);
            }
        }
        __syncthreads();
    }
}

// ============ generic GEMM kernel: EPI 0 plain, 1 +R, 2 relu^2 ============
template <int EPI>
__global__ __launch_bounds__(256, 2) void gemm_mma(const float* __restrict__ A,
                                                   const float* __restrict__ W,
                                                   const float* __restrict__ R,
                                                   float* __restrict__ Out,
                                                   int M, int N, int K) {
    extern __shared__ float sm[];
    const int bm = blockIdx.y * 128, bn = blockIdx.x * 128;
    GemmAcc G;
    gemm_mainloop(A, W, M, N, K, bm, bn, sm, G);

    const int tid = threadIdx.x;
    const int warp = tid >> 5, lane = tid & 31;
    const int wy = warp >> 1, wx = warp & 1;
    const int gid = lane >> 2, tig = lane & 3;

    #pragma unroll
    for (int i = 0; i < 2; i++) {
        const int r0 = bm + wy * 32 + i * 16 + gid;
        const int r1 = r0 + 8;
        #pragma unroll
        for (int j = 0; j < 8; j++) {
            const int cc = bn + wx * 64 + j * 8 + 2 * tig;
            float v0 = G.c[i][j][0], v1 = G.c[i][j][1];
            float v2 = G.c[i][j][2], v3 = G.c[i][j][3];
            if (EPI == 1) {
                float2 t0 = *(const float2*)(R + (size_t)r0 * N + cc);
                float2 t1 = *(const float2*)(R + (size_t)r1 * N + cc);
                v0 += t0.x; v1 += t0.y; v2 += t1.x; v3 += t1.y;
            }
            if (EPI == 2) {
                v0 = fmaxf(v0, 0.f); v0 *= v0;
                v1 = fmaxf(v1, 0.f); v1 *= v1;
                v2 = fmaxf(v2, 0.f); v2 *= v2;
                v3 = fmaxf(v3, 0.f); v3 *= v3;
            }
            *(float2*)(Out + (size_t)r0 * N + cc) = make_float2(v0, v1);
            *(float2*)(Out + (size_t)r1 * N + cc) = make_float2(v2, v3);
        }
    }
}

// ============ fused QKV GEMM with RoPE epilogue ============
__global__ __launch_bounds__(256, 2) void qkv_gemm(const float* __restrict__ A,
                                                   const float* __restrict__ wq,
                                                   const float* __restrict__ wk,
                                                   const float* __restrict__ wv,
                                                   const float* __restrict__ cs,
                                                   const float* __restrict__ sn,
                                                   float* __restrict__ q,
                                                   float* __restrict__ k,
                                                   float* __restrict__ v) {
    extern __shared__ float sm[];
    const int mat = blockIdx.x / 6;
    const int bn = (blockIdx.x % 6) * 128;
    const int bm = blockIdx.y * 128;
    const float* W = (mat == 0) ? wq : (mat == 1) ? wk : wv;
    float* Out = (mat == 0) ? q : (mat == 1) ? k : v;

    GemmAcc G;
    gemm_mainloop(A, W, NROWS, CD, CD, bm, bn, sm, G);

    const int tid = threadIdx.x;
    const int warp = tid >> 5, lane = tid & 31;
    const int wy = warp >> 1, wx = warp & 1;
    const int gid = lane >> 2, tig = lane & 3;

    if (mat == 2) {
        #pragma unroll
        for (int i = 0; i < 2; i++) {
            const int r0 = bm + wy * 32 + i * 16 + gid;
            const int r1 = r0 + 8;
            #pragma unroll
            for (int j = 0; j < 8; j++) {
                const int cc = bn + wx * 64 + j * 8 + 2 * tig;
                *(float2*)(Out + (size_t)r0 * CD + cc) = make_float2(G.c[i][j][0], G.c[i][j][1]);
                *(float2*)(Out + (size_t)r1 * CD + cc) = make_float2(G.c[i][j][2], G.c[i][j][3]);
            }
        }
    } else {
        #pragma unroll
        for (int i = 0; i < 2; i++) {
            const int r0 = bm + wy * 32 + i * 16 + gid;
            const int r1 = r0 + 8;
            const int t0 = r0 & (TT - 1), t1 = r1 & (TT - 1);
            #pragma unroll
            for (int j = 0; j < 4; j++) {
                const int d = j * 8 + 2 * tig;
                const int cc = bn + wx * 64 + j * 8 + 2 * tig;
                float2 c0 = *(const float2*)(cs + t0 * DD2 + d);
                float2 s0 = *(const float2*)(sn + t0 * DD2 + d);
                float2 c1 = *(const float2*)(cs + t1 * DD2 + d);
                float2 s1 = *(const float2*)(sn + t1 * DD2 + d);
                float x1a = G.c[i][j][0], x1b = G.c[i][j][1];
                float x2a = G.c[i][j + 4][0], x2b = G.c[i][j + 4][1];
                *(float2*)(Out + (size_t)r0 * CD + cc) =
                    make_float2(x1a * c0.x + x2a * s0.x, x1b * c0.y + x2b * s0.y);
                *(float2*)(Out + (size_t)r0 * CD + cc + 32) =
                    make_float2(-x1a * s0.x + x2a * c0.x, -x1b * s0.y + x2b * c0.y);
                float y1a = G.c[i][j][2], y1b = G.c[i][j][3];
                float y2a = G.c[i][j + 4][2], y2b = G.c[i][j + 4][3];
                *(float2*)(Out + (size_t)r1 * CD + cc) =
                    make_float2(y1a * c1.x + y2a * s1.x, y1b * c1.y + y2b * s1.y);
                *(float2*)(Out + (size_t)r1 * CD + cc + 32) =
                    make_float2(-y1a * s1.x + y2a * c1.x, -y1b * s1.y + y2b * c1.y);
            }
        }
    }
}

// ---------------- RMSNorm ----------------
__global__ __launch_bounds__(256) void rmsnorm_kernel(const float* __restrict__ x,
                                                      const float* __restrict__ g,
                                                      float* __restrict__ out) {
    int row = blockIdx.x;
    const float* xr = x + (size_t)row * CD;
    float ss = 0.f;
    for (int i = threadIdx.x; i < CD; i += 256) { float v = xr[i]; ss += v * v; }
    #pragma unroll
    for (int o = 16; o; o >>= 1) ss += __shfl_xor_sync(0xffffffffu, ss, o);
    __shared__ float red[8];
    if ((threadIdx.x & 31) == 0) red[threadIdx.x >> 5] = ss;
    __syncthreads();
    float tot = 0.f;
    #pragma unroll
    for (int i = 0; i < 8; i++) tot += red[i];
    float rinv = rsqrtf(tot / (float)CD + kEPS);
    float* orow = out + (size_t)row * CD;
    for (int i = threadIdx.x; i < CD; i += 256) orow[i] = g[i] * xr[i] * rinv;
}

// ---------------- Tensor-core Flash Attention ----------------
// CTA: 128 threads (4 warps), 64 q-rows x one (b,h). Warp owns 16 q-rows.
// smem: sQP [64][68] (Q staging -> per-warp P slices), sK [64][68], sV [64][72]
#define ST_K 68
#define ST_V 72
#define ATTN_SMEM ((64*ST_K + 64*ST_K + 64*ST_V) * 4)
__global__ __launch_bounds__(128, 3) void attn_mma(const float* __restrict__ q,
                                                   const float* __restrict__ k,
                                                   const float* __restrict__ v,
                                                   float* __restrict__ y) {
    extern __shared__ float asm_[];
    uint32_t* uQP = (uint32_t*)asm_;             // [64][68]
    uint32_t* uK  = uQP + 64 * ST_K;             // [64][68]
    uint32_t* uV  = uK + 64 * ST_K;              // [64][72]

    const int qt = blockIdx.x, h = blockIdx.y, b = blockIdx.z;
    const int tid = threadIdx.x, warp = tid >> 5, lane = tid & 31;
    const int gid = lane >> 2, tig = lane & 3;
    const int qs = qt * 64;
    const size_t bh = (size_t)b * TT * CD + (size_t)h * HDIM;

    // stage Q (scaled by 1/8, tf32)
    for (int i = tid; i < 64 * 16; i += 128) {
        int r = i >> 4, c4 = (i & 15) * 4;
        float4 vq = *(const float4*)(q + bh + (size_t)(qs + r) * CD + c4);
        uint32_t* d = uQP + r * ST_K + c4;
        d[0] = f2tf32(vq.x * 0.125f); d[1] = f2tf32(vq.y * 0.125f);
        d[2] = f2tf32(vq.z * 0.125f); d[3] = f2tf32(vq.w * 0.125f);
    }
    __syncthreads();

    // extract Q fragments (register-resident)
    uint32_t qf[8][4];
    {
        const int r0 = warp * 16 + gid;
        #pragma unroll
        for (int kb = 0; kb < 8; kb++) {
            qf[kb][0] = uQP[r0 * ST_K + kb * 8 + tig];
            qf[kb][1] = uQP[(r0 + 8) * ST_K + kb * 8 + tig];
            qf[kb][2] = uQP[r0 * ST_K + kb * 8 + tig + 4];
            qf[kb][3] = uQP[(r0 + 8) * ST_K + kb * 8 + tig + 4];
        }
    }

    float m[2] = {-1e30f, -1e30f}, l[2] = {0.f, 0.f};
    float o[8][4];
    #pragma unroll
    for (int j = 0; j < 8; j++)
        #pragma unroll
        for (int t = 0; t < 4; t++) o[j][t] = 0.f;

    uint32_t* uP = uQP + warp * 16 * ST_K;   // per-warp P slice [16][68]

    for (int kt = 0; kt <= qt; kt++) {
        const int ks = kt * 64;
        __syncthreads();   // all warps done with sK/sV (and warp-private P reuse of sQP is safe)
        for (int i = tid; i < 64 * 16; i += 128) {
            int r = i >> 4, c4 = (i & 15) * 4;
            float4 vk = *(const float4*)(k + bh + (size_t)(ks + r) * CD + c4);
            uint32_t* dk = uK + r * ST_K + c4;
            dk[0] = f2tf32(vk.x); dk[1] = f2tf32(vk.y);
            dk[2] = f2tf32(vk.z); dk[3] = f2tf32(vk.w);
            float4 vv = *(const float4*)(v + bh + (size_t)(ks + r) * CD + c4);
            uint32_t* dv = uV + r * ST_V + c4;
            dv[0] = f2tf32(vv.x); dv[1] = f2tf32(vv.y);
            dv[2] = f2tf32(vv.z); dv[3] = f2tf32(vv.w);
        }
        __syncthreads();

        // S = (Q/8) K^T : warp-tile 16 x 64
        float sf[8][4];
        #pragma unroll
        for (int j = 0; j < 8; j++)
            #pragma unroll
            for (int t = 0; t < 4; t++) sf[j][t] = 0.f;
        #pragma unroll
        for (int kb = 0; kb < 8; kb++) {
            #pragma unroll
            for (int j = 0; j < 8; j++) {
                uint32_t bf[2];
                bf[0] = uK[(j * 8 + gid) * ST_K + kb * 8 + tig];
                bf[1] = uK[(j * 8 + gid) * ST_K + kb * 8 + tig + 4];
                mma_tf32(sf[j], qf[kb], bf);
            }
        }

        // causal mask on diagonal tile
        if (kt == qt) {
            const int qr0 = warp * 16 + gid, qr1 = qr0 + 8;
            #pragma unroll
            for (int j = 0; j < 8; j++) {
                const int kc = j * 8 + 2 * tig;
                if (kc > qr0)     sf[j][0] = -1e30f;
                if (kc + 1 > qr0) sf[j][1] = -1e30f;
                if (kc > qr1)     sf[j][2] = -1e30f;
                if (kc + 1 > qr1) sf[j][3] = -1e30f;
            }
        }

        // online softmax (rows gid, gid+8); quad lanes share a row
        #pragma unroll
        for (int r = 0; r < 2; r++) {
            float mx = -1e30f;
            #pragma unroll
            for (int j = 0; j < 8; j++)
                mx = fmaxf(mx, fmaxf(sf[j][2 * r], sf[j][2 * r + 1]));
            mx = fmaxf(mx, __shfl_xor_sync(0xffffffffu, mx, 1));
            mx = fmaxf(mx, __shfl_xor_sync(0xffffffffu, mx, 2));
            const float mnew = fmaxf(m[r], mx);
            const float alpha = __expf(m[r] - mnew);
            float rs = 0.f;
            #pragma unroll
            for (int j = 0; j < 8; j++) {
                float p0 = __expf(sf[j][2 * r] - mnew);
                float p1 = __expf(sf[j][2 * r + 1] - mnew);
                sf[j][2 * r] = p0; sf[j][2 * r + 1] = p1;
                rs += p0 + p1;
            }
            rs += __shfl_xor_sync(0xffffffffu, rs, 1);
            rs += __shfl_xor_sync(0xffffffffu, rs, 2);
            l[r] = l[r] * alpha + rs;
            m[r] = mnew;
            #pragma unroll
            for (int j = 0; j < 8; j++) { o[j][2 * r] *= alpha; o[j][2 * r + 1] *= alpha; }
        }

        // store P (tf32) to warp-private slice
        #pragma unroll
        for (int j = 0; j < 8; j++) {
            uint32_t* d0 = uP + gid * ST_K + j * 8 + 2 * tig;
            d0[0] = f2tf32(sf[j][0]); d0[1] = f2tf32(sf[j][1]);
            uint32_t* d1 = uP + (gid + 8) * ST_K + j * 8 + 2 * tig;
            d1[0] = f2tf32(sf[j][2]); d1[1] = f2tf32(sf[j][3]);
        }
        __syncwarp();

        // O += P V
        #pragma unroll
        for (int kb = 0; kb < 8; kb++) {
            uint32_t pa[4];
            pa[0] = uP[gid * ST_K + kb * 8 + tig];
            pa[1] = uP[(gid + 8) * ST_K + kb * 8 + tig];
            pa[2] = uP[gid * ST_K + kb * 8 + tig + 4];
            pa[3] = uP[(gid + 8) * ST_K + kb * 8 + tig + 4];
            #pragma unroll
            for (int j = 0; j < 8; j++) {
                uint32_t vb[2];
                vb[0] = uV[(kb * 8 + tig) * ST_V + j * 8 + gid];
                vb[1] = uV[(kb * 8 + tig + 4) * ST_V + j * 8 + gid];
                mma_tf32(o[j], pa, vb);
            }
        }
        __syncwarp();   // P reads done before next iteration's P write
    }

    // write O = acc / l
    const float inv0 = 1.f / l[0], inv1 = 1.f / l[1];
    const int qa0 = qs + warp * 16 + gid, qa1 = qa0 + 8;
    #pragma unroll
    for (int j = 0; j < 8; j++) {
        const int cc = j * 8 + 2 * tig;
        *(float2*)(y + bh + (size_t)qa0 * CD + cc) = make_float2(o[j][0] * inv0, o[j][1] * inv0);
        *(float2*)(y + bh + (size_t)qa1 * CD + cc) = make_float2(o[j][2] * inv1, o[j][3] * inv1);
    }
}

// ---------------- launch ----------------
extern "C" void kernel_launch(void* const* d_in, const int* in_sizes, int n_in,
                              void* d_out, int out_size) {
    const float* x   = (const float*)d_in[0];
    const float* cs  = (const float*)d_in[1];
    const float* sn  = (const float*)d_in[2];
    const float* wq  = (const float*)d_in[3];
    const float* wk  = (const float*)d_in[4];
    const float* wv  = (const float*)d_in[5];
    const float* wo  = (const float*)d_in[6];
    const float* wfc = (const float*)d_in[7];
    const float* wpr = (const float*)d_in[8];
    const float* g1  = (const float*)d_in[9];
    const float* g2  = (const float*)d_in[10];
    float* out = (float*)d_out;

    float *h, *q, *k, *v, *y, *x2, *ff;
    cudaGetSymbolAddress((void**)&h,  g_h);
    cudaGetSymbolAddress((void**)&q,  g_q);
    cudaGetSymbolAddress((void**)&k,  g_k);
    cudaGetSymbolAddress((void**)&v,  g_v);
    cudaGetSymbolAddress((void**)&y,  g_y);
    cudaGetSymbolAddress((void**)&x2, g_x2);
    cudaGetSymbolAddress((void**)&ff, g_ff);

    cudaFuncSetAttribute((const void*)attn_mma,
                         cudaFuncAttributeMaxDynamicSharedMemorySize, ATTN_SMEM);
    cudaFuncSetAttribute((const void*)qkv_gemm,
                         cudaFuncAttributeMaxDynamicSharedMemorySize, GEMM_SMEM);
    cudaFuncSetAttribute((const void*)gemm_mma<0>,
                         cudaFuncAttributeMaxDynamicSharedMemorySize, GEMM_SMEM);
    cudaFuncSetAttribute((const void*)gemm_mma<1>,
                         cudaFuncAttributeMaxDynamicSharedMemorySize, GEMM_SMEM);
    cudaFuncSetAttribute((const void*)gemm_mma<2>,
                         cudaFuncAttributeMaxDynamicSharedMemorySize, GEMM_SMEM);

    // 1. h = rmsnorm(x, g1)
    rmsnorm_kernel<<<NROWS, 256>>>(x, g1, h);

    // 2+3. q,k,v = h @ {wq,wk,wv}, RoPE fused
    qkv_gemm<<<dim3(18, 32), 256, GEMM_SMEM>>>(h, wq, wk, wv, cs, sn, q, k, v);

    // 4. attention -> y
    attn_mma<<<dim3(TT / 64, HH, BB), 128, ATTN_SMEM>>>(q, k, v, y);

    // 5. x2 = x + y @ wo
    dim3 gCC(CD / 128, NROWS / 128);
    gemm_mma<1><<<gCC, 256, GEMM_SMEM>>>(y, wo, x, x2, NROWS, CD, CD);

    // 6. h = rmsnorm(x2, g2)
    rmsnorm_kernel<<<NROWS, 256>>>(x2, g2, h);

    // 7. ff = relu(h @ wfc)^2
    dim3 gFC(FFD / 128, NROWS / 128);
    gemm_mma<2><<<gFC, 256, GEMM_SMEM>>>(h, wfc, nullptr, ff, NROWS, FFD, CD);

    // 8. out = x2 + ff @ wpr
    gemm_mma<1><<<gCC, 256, GEMM_SMEM>>>(ff, wpr, x2, out, NROWS, CD, FFD);
}

// round 5
// speedup vs baseline: 3.1108x; 1.0002x over previous
#include <cuda_runtime.h>
#include <math.h>
#include <stdint.h>

// Problem constants
#define BB 2
#define TT 2048
#define CD 768
#define HH 12
#define HDIM 64
#define DD2 32
#define FFD 3072
#define NROWS (BB*TT)          // 4096
static __device__ __constant__ float kEPS = 1e-5f;

// ---------------- scratch ----------------
__device__ float g_h [NROWS*CD];
__device__ float g_q [NROWS*CD];
__device__ float g_k [NROWS*CD];
__device__ float g_v [NROWS*CD];
__device__ float g_y [NROWS*CD];
__device__ float g_x2[NROWS*CD];
__device__ float g_ff[NROWS*FFD];

// ---------------- mma.sync tf32 helpers ----------------
__device__ __forceinline__ uint32_t f2tf32(float f) {
    uint32_t r;
    asm("cvt.rna.tf32.f32 %0, %1;" : "=r"(r) : "f"(f));
    return r;
}
__device__ __forceinline__ void mma_tf32(float* c, const uint32_t* a, const uint32_t* b) {
    asm volatile(
        "mma.sync.aligned.m16n8k8.row.col.f32.tf32.tf32.f32 "
        "{%0,%1,%2,%3}, {%4,%5,%6,%7}, {%8,%9}, {%0,%1,%2,%3};"
        : "+f"(c[0]), "+f"(c[1]), "+f"(c[2]), "+f"(c[3])
        : "r"(a[0]), "r"(a[1]), "r"(a[2]), "r"(a[3]), "r"(b[0]), "r"(b[1]));
}
__device__ __forceinline__ uint32_t smem_u32(const void* p) {
    uint32_t a;
    asm("{ .reg .u64 t; cvta.to.shared.u64 t, %1; cvt.u32.u64 %0, t; }" : "=r"(a) : "l"(p));
    return a;
}
__device__ __forceinline__ void cp16(uint32_t dst, const float* src) {
    asm volatile("cp.async.cg.shared.global [%0], [%1], 16;" :: "r"(dst), "l"(src));
}
#define CP_COMMIT() asm volatile("cp.async.commit_group;" ::: "memory")
#define CP_WAIT1()  asm volatile("cp.async.wait_group 1;" ::: "memory")

// SMEM pipeline geometry (floats): A [128][36], B [32][136], 3 stages
#define ST_A 36
#define ST_B 136
#define A_STAGE (128 * ST_A)                 // 4608 floats
#define B_STAGE (32 * ST_B)                  // 4352 floats
#define STAGE_FLOATS (A_STAGE + B_STAGE)     // 8960 floats = 35840 B
#define NSTAGE 3
#define GEMM_SMEM (NSTAGE * STAGE_FLOATS * 4) // 107520 B

// ============ GEMM core: CTA 128x128, 256 thr, warp tile 32x64, cp.async 3-stage ============
struct GemmAcc { float c[2][8][4]; };

__device__ __forceinline__ void gemm_mainloop(const float* __restrict__ A,
                                              const float* __restrict__ W,
                                              int M, int N, int K,
                                              int bm, int bn, float* sm,
                                              GemmAcc& G) {
    const int tid = threadIdx.x;
    const int warp = tid >> 5, lane = tid & 31;
    const int wy = warp >> 1, wx = warp & 1;
    const int gid = lane >> 2, tig = lane & 3;

    #pragma unroll
    for (int i = 0; i < 2; i++)
        #pragma unroll
        for (int j = 0; j < 8; j++)
            #pragma unroll
            for (int t = 0; t < 4; t++) G.c[i][j][t] = 0.f;

    const int NC = K >> 5;
    const uint32_t sbase = smem_u32(sm);

    // staging maps (per thread: 4 A granules + 4 B granules of 16B)
    const int ar = tid >> 1, ag = (tid & 1) * 4;   // A: row 0..127, granule base 0/4
    const int bk = tid >> 3, bg = tid & 7;         // B: k-row 0..31, granule base 0..7
    const float* Abase = A + (size_t)(bm + ar) * K + ag * 4;
    const float* Wbase = W + (size_t)bk * N + bn + bg * 4;
    const uint32_t aOff = (uint32_t)(ar * (ST_A * 4) + ag * 16);
    const uint32_t bOff = (uint32_t)(A_STAGE * 4 + bk * (ST_B * 4) + bg * 16);

    // prologue: stages 0 and 1
    #pragma unroll
    for (int s = 0; s < 2; s++) {
        const uint32_t st = sbase + s * (STAGE_FLOATS * 4);
        const float* Ac = Abase + s * 32;
        #pragma unroll
        for (int p = 0; p < 4; p++) cp16(st + aOff + p * 16, Ac + p * 4);
        const float* Wc = Wbase + (size_t)s * 32 * N;
        #pragma unroll
        for (int p = 0; p < 4; p++) cp16(st + bOff + p * 128, Wc + p * 32);
        CP_COMMIT();
    }

    int s = 0;
    for (int c = 0; c < NC; c++) {
        CP_WAIT1();
        __syncthreads();
        // issue chunk c+2 into stage (s+2)%3
        if (c + 2 < NC) {
            const int s2 = (s + 2 >= NSTAGE) ? s + 2 - NSTAGE : s + 2;
            const uint32_t st = sbase + s2 * (STAGE_FLOATS * 4);
            const float* Ac = Abase + (c + 2) * 32;
            #pragma unroll
            for (int p = 0; p < 4; p++) cp16(st + aOff + p * 16, Ac + p * 4);
            const float* Wc = Wbase + (size_t)(c + 2) * 32 * N;
            #pragma unroll
            for (int p = 0; p < 4; p++) cp16(st + bOff + p * 128, Wc + p * 32);
        }
        CP_COMMIT();

        // compute on stage s
        const float* sA = sm + s * STAGE_FLOATS;
        const float* sB = sA + A_STAGE;
        #pragma unroll
        for (int ks = 0; ks < 4; ks++) {
            const int kb = ks * 8;
            uint32_t af[2][4];
            #pragma unroll
            for (int i = 0; i < 2; i++) {
                const int r0 = wy * 32 + i * 16 + gid;
                af[i][0] = f2tf32(sA[r0 * ST_A + kb + tig]);
                af[i][1] = f2tf32(sA[(r0 + 8) * ST_A + kb + tig]);
                af[i][2] = f2tf32(sA[r0 * ST_A + kb + tig + 4]);
                af[i][3] = f2tf32(sA[(r0 + 8) * ST_A + kb + tig + 4]);
            }
            uint32_t bf[8][2];
            #pragma unroll
            for (int j = 0; j < 8; j++) {
                const int cb = wx * 64 + j * 8;
                bf[j][0] = f2tf32(sB[(kb + tig) * ST_B + cb + gid]);
                bf[j][1] = f2tf32(sB[(kb + tig + 4) * ST_B + cb + gid]);
            }
            #pragma unroll
            for (int i = 0; i < 2; i++)
                #pragma unroll
                for (int j = 0; j < 8; j++) mma_tf32(G.c[i][j], af[i], bf[j]);
        }
        s = (s + 1 >= NSTAGE) ? 0 : s + 1;
    }
}

// ============ generic GEMM kernel: EPI 0 plain, 1 +R, 2 relu^2 ============
template <int EPI>
__global__ __launch_bounds__(256, 2) void gemm_mma(const float* __restrict__ A,
                                                   const float* __restrict__ W,
                                                   const float* __restrict__ R,
                                                   float* __restrict__ Out,
                                                   int M, int N, int K) {
    extern __shared__ float sm[];
    const int bm = blockIdx.y * 128, bn = blockIdx.x * 128;
    GemmAcc G;
    gemm_mainloop(A, W, M, N, K, bm, bn, sm, G);

    const int tid = threadIdx.x;
    const int warp = tid >> 5, lane = tid & 31;
    const int wy = warp >> 1, wx = warp & 1;
    const int gid = lane >> 2, tig = lane & 3;

    #pragma unroll
    for (int i = 0; i < 2; i++) {
        const int r0 = bm + wy * 32 + i * 16 + gid;
        const int r1 = r0 + 8;
        #pragma unroll
        for (int j = 0; j < 8; j++) {
            const int cc = bn + wx * 64 + j * 8 + 2 * tig;
            float v0 = G.c[i][j][0], v1 = G.c[i][j][1];
            float v2 = G.c[i][j][2], v3 = G.c[i][j][3];
            if (EPI == 1) {
                float2 t0 = *(const float2*)(R + (size_t)r0 * N + cc);
                float2 t1 = *(const float2*)(R + (size_t)r1 * N + cc);
                v0 += t0.x; v1 += t0.y; v2 += t1.x; v3 += t1.y;
            }
            if (EPI == 2) {
                v0 = fmaxf(v0, 0.f); v0 *= v0;
                v1 = fmaxf(v1, 0.f); v1 *= v1;
                v2 = fmaxf(v2, 0.f); v2 *= v2;
                v3 = fmaxf(v3, 0.f); v3 *= v3;
            }
            *(float2*)(Out + (size_t)r0 * N + cc) = make_float2(v0, v1);
            *(float2*)(Out + (size_t)r1 * N + cc) = make_float2(v2, v3);
        }
    }
}

// ============ fused QKV GEMM with RoPE epilogue ============
__global__ __launch_bounds__(256, 2) void qkv_gemm(const float* __restrict__ A,
                                                   const float* __restrict__ wq,
                                                   const float* __restrict__ wk,
                                                   const float* __restrict__ wv,
                                                   const float* __restrict__ cs,
                                                   const float* __restrict__ sn,
                                                   float* __restrict__ q,
                                                   float* __restrict__ k,
                                                   float* __restrict__ v) {
    extern __shared__ float sm[];
    const int mat = blockIdx.x / 6;
    const int bn = (blockIdx.x % 6) * 128;
    const int bm = blockIdx.y * 128;
    const float* W = (mat == 0) ? wq : (mat == 1) ? wk : wv;
    float* Out = (mat == 0) ? q : (mat == 1) ? k : v;

    GemmAcc G;
    gemm_mainloop(A, W, NROWS, CD, CD, bm, bn, sm, G);

    const int tid = threadIdx.x;
    const int warp = tid >> 5, lane = tid & 31;
    const int wy = warp >> 1, wx = warp & 1;
    const int gid = lane >> 2, tig = lane & 3;

    if (mat == 2) {
        #pragma unroll
        for (int i = 0; i < 2; i++) {
            const int r0 = bm + wy * 32 + i * 16 + gid;
            const int r1 = r0 + 8;
            #pragma unroll
            for (int j = 0; j < 8; j++) {
                const int cc = bn + wx * 64 + j * 8 + 2 * tig;
                *(float2*)(Out + (size_t)r0 * CD + cc) = make_float2(G.c[i][j][0], G.c[i][j][1]);
                *(float2*)(Out + (size_t)r1 * CD + cc) = make_float2(G.c[i][j][2], G.c[i][j][3]);
            }
        }
    } else {
        #pragma unroll
        for (int i = 0; i < 2; i++) {
            const int r0 = bm + wy * 32 + i * 16 + gid;
            const int r1 = r0 + 8;
            const int t0 = r0 & (TT - 1), t1 = r1 & (TT - 1);
            #pragma unroll
            for (int j = 0; j < 4; j++) {
                const int d = j * 8 + 2 * tig;
                const int cc = bn + wx * 64 + j * 8 + 2 * tig;
                float2 c0 = *(const float2*)(cs + t0 * DD2 + d);
                float2 s0 = *(const float2*)(sn + t0 * DD2 + d);
                float2 c1 = *(const float2*)(cs + t1 * DD2 + d);
                float2 s1 = *(const float2*)(sn + t1 * DD2 + d);
                float x1a = G.c[i][j][0], x1b = G.c[i][j][1];
                float x2a = G.c[i][j + 4][0], x2b = G.c[i][j + 4][1];
                *(float2*)(Out + (size_t)r0 * CD + cc) =
                    make_float2(x1a * c0.x + x2a * s0.x, x1b * c0.y + x2b * s0.y);
                *(float2*)(Out + (size_t)r0 * CD + cc + 32) =
                    make_float2(-x1a * s0.x + x2a * c0.x, -x1b * s0.y + x2b * c0.y);
                float y1a = G.c[i][j][2], y1b = G.c[i][j][3];
                float y2a = G.c[i][j + 4][2], y2b = G.c[i][j + 4][3];
                *(float2*)(Out + (size_t)r1 * CD + cc) =
                    make_float2(y1a * c1.x + y2a * s1.x, y1b * c1.y + y2b * s1.y);
                *(float2*)(Out + (size_t)r1 * CD + cc + 32) =
                    make_float2(-y1a * s1.x + y2a * c1.x, -y1b * s1.y + y2b * c1.y);
            }
        }
    }
}

// ---------------- RMSNorm ----------------
__global__ __launch_bounds__(256) void rmsnorm_kernel(const float* __restrict__ x,
                                                      const float* __restrict__ g,
                                                      float* __restrict__ out) {
    int row = blockIdx.x;
    const float* xr = x + (size_t)row * CD;
    float ss = 0.f;
    for (int i = threadIdx.x; i < CD; i += 256) { float v = xr[i]; ss += v * v; }
    #pragma unroll
    for (int o = 16; o; o >>= 1) ss += __shfl_xor_sync(0xffffffffu, ss, o);
    __shared__ float red[8];
    if ((threadIdx.x & 31) == 0) red[threadIdx.x >> 5] = ss;
    __syncthreads();
    float tot = 0.f;
    #pragma unroll
    for (int i = 0; i < 8; i++) tot += red[i];
    float rinv = rsqrtf(tot / (float)CD + kEPS);
    float* orow = out + (size_t)row * CD;
    for (int i = threadIdx.x; i < CD; i += 256) orow[i] = g[i] * xr[i] * rinv;
}

// ---------------- Tensor-core Flash Attention ----------------
#define AST_K 68
#define AST_V 72
#define ATTN_SMEM ((64*AST_K + 64*AST_K + 64*AST_V) * 4)
__global__ __launch_bounds__(128, 3) void attn_mma(const float* __restrict__ q,
                                                   const float* __restrict__ k,
                                                   const float* __restrict__ v,
                                                   float* __restrict__ y) {
    extern __shared__ float asm_[];
    uint32_t* uQP = (uint32_t*)asm_;             // [64][68]
    uint32_t* uK  = uQP + 64 * AST_K;            // [64][68]
    uint32_t* uV  = uK + 64 * AST_K;             // [64][72]

    const int qt = blockIdx.x, h = blockIdx.y, b = blockIdx.z;
    const int tid = threadIdx.x, warp = tid >> 5, lane = tid & 31;
    const int gid = lane >> 2, tig = lane & 3;
    const int qs = qt * 64;
    const size_t bh = (size_t)b * TT * CD + (size_t)h * HDIM;

    for (int i = tid; i < 64 * 16; i += 128) {
        int r = i >> 4, c4 = (i & 15) * 4;
        float4 vq = *(const float4*)(q + bh + (size_t)(qs + r) * CD + c4);
        uint32_t* d = uQP + r * AST_K + c4;
        d[0] = f2tf32(vq.x * 0.125f); d[1] = f2tf32(vq.y * 0.125f);
        d[2] = f2tf32(vq.z * 0.125f); d[3] = f2tf32(vq.w * 0.125f);
    }
    __syncthreads();

    uint32_t qf[8][4];
    {
        const int r0 = warp * 16 + gid;
        #pragma unroll
        for (int kb = 0; kb < 8; kb++) {
            qf[kb][0] = uQP[r0 * AST_K + kb * 8 + tig];
            qf[kb][1] = uQP[(r0 + 8) * AST_K + kb * 8 + tig];
            qf[kb][2] = uQP[r0 * AST_K + kb * 8 + tig + 4];
            qf[kb][3] = uQP[(r0 + 8) * AST_K + kb * 8 + tig + 4];
        }
    }

    float m[2] = {-1e30f, -1e30f}, l[2] = {0.f, 0.f};
    float o[8][4];
    #pragma unroll
    for (int j = 0; j < 8; j++)
        #pragma unroll
        for (int t = 0; t < 4; t++) o[j][t] = 0.f;

    uint32_t* uP = uQP + warp * 16 * AST_K;

    for (int kt = 0; kt <= qt; kt++) {
        const int ks = kt * 64;
        __syncthreads();
        for (int i = tid; i < 64 * 16; i += 128) {
            int r = i >> 4, c4 = (i & 15) * 4;
            float4 vk = *(const float4*)(k + bh + (size_t)(ks + r) * CD + c4);
            uint32_t* dk = uK + r * AST_K + c4;
            dk[0] = f2tf32(vk.x); dk[1] = f2tf32(vk.y);
            dk[2] = f2tf32(vk.z); dk[3] = f2tf32(vk.w);
            float4 vv = *(const float4*)(v + bh + (size_t)(ks + r) * CD + c4);
            uint32_t* dv = uV + r * AST_V + c4;
            dv[0] = f2tf32(vv.x); dv[1] = f2tf32(vv.y);
            dv[2] = f2tf32(vv.z); dv[3] = f2tf32(vv.w);
        }
        __syncthreads();

        float sf[8][4];
        #pragma unroll
        for (int j = 0; j < 8; j++)
            #pragma unroll
            for (int t = 0; t < 4; t++) sf[j][t] = 0.f;
        #pragma unroll
        for (int kb = 0; kb < 8; kb++) {
            #pragma unroll
            for (int j = 0; j < 8; j++) {
                uint32_t bf[2];
                bf[0] = uK[(j * 8 + gid) * AST_K + kb * 8 + tig];
                bf[1] = uK[(j * 8 + gid) * AST_K + kb * 8 + tig + 4];
                mma_tf32(sf[j], qf[kb], bf);
            }
        }

        if (kt == qt) {
            const int qr0 = warp * 16 + gid, qr1 = qr0 + 8;
            #pragma unroll
            for (int j = 0; j < 8; j++) {
                const int kc = j * 8 + 2 * tig;
                if (kc > qr0)     sf[j][0] = -1e30f;
                if (kc + 1 > qr0) sf[j][1] = -1e30f;
                if (kc > qr1)     sf[j][2] = -1e30f;
                if (kc + 1 > qr1) sf[j][3] = -1e30f;
            }
        }

        #pragma unroll
        for (int r = 0; r < 2; r++) {
            float mx = -1e30f;
            #pragma unroll
            for (int j = 0; j < 8; j++)
                mx = fmaxf(mx, fmaxf(sf[j][2 * r], sf[j][2 * r + 1]));
            mx = fmaxf(mx, __shfl_xor_sync(0xffffffffu, mx, 1));
            mx = fmaxf(mx, __shfl_xor_sync(0xffffffffu, mx, 2));
            const float mnew = fmaxf(m[r], mx);
            const float alpha = __expf(m[r] - mnew);
            float rs = 0.f;
            #pragma unroll
            for (int j = 0; j < 8; j++) {
                float p0 = __expf(sf[j][2 * r] - mnew);
                float p1 = __expf(sf[j][2 * r + 1] - mnew);
                sf[j][2 * r] = p0; sf[j][2 * r + 1] = p1;
                rs += p0 + p1;
            }
            rs += __shfl_xor_sync(0xffffffffu, rs, 1);
            rs += __shfl_xor_sync(0xffffffffu, rs, 2);
            l[r] = l[r] * alpha + rs;
            m[r] = mnew;
            #pragma unroll
            for (int j = 0; j < 8; j++) { o[j][2 * r] *= alpha; o[j][2 * r + 1] *= alpha; }
        }

        #pragma unroll
        for (int j = 0; j < 8; j++) {
            uint32_t* d0 = uP + gid * AST_K + j * 8 + 2 * tig;
            d0[0] = f2tf32(sf[j][0]); d0[1] = f2tf32(sf[j][1]);
            uint32_t* d1 = uP + (gid + 8) * AST_K + j * 8 + 2 * tig;
            d1[0] = f2tf32(sf[j][2]); d1[1] = f2tf32(sf[j][3]);
        }
        __syncwarp();

        #pragma unroll
        for (int kb = 0; kb < 8; kb++) {
            uint32_t pa[4];
            pa[0] = uP[gid * AST_K + kb * 8 + tig];
            pa[1] = uP[(gid + 8) * AST_K + kb * 8 + tig];
            pa[2] = uP[gid * AST_K + kb * 8 + tig + 4];
            pa[3] = uP[(gid + 8) * AST_K + kb * 8 + tig + 4];
            #pragma unroll
            for (int j = 0; j < 8; j++) {
                uint32_t vb[2];
                vb[0] = uV[(kb * 8 + tig) * AST_V + j * 8 + gid];
                vb[1] = uV[(kb * 8 + tig + 4) * AST_V + j * 8 + gid];
                mma_tf32(o[j], pa, vb);
            }
        }
        __syncwarp();
    }

    const float inv0 = 1.f / l[0], inv1 = 1.f / l[1];
    const int qa0 = qs + warp * 16 + gid, qa1 = qa0 + 8;
    #pragma unroll
    for (int j = 0; j < 8; j++) {
        const int cc = j * 8 + 2 * tig;
        *(float2*)(y + bh + (size_t)qa0 * CD + cc) = make_float2(o[j][0] * inv0, o[j][1] * inv0);
        *(float2*)(y + bh + (size_t)qa1 * CD + cc) = make_float2(o[j][2] * inv1, o[j][3] * inv1);
    }
}

// ---------------- launch ----------------
extern "C" void kernel_launch(void* const* d_in, const int* in_sizes, int n_in,
                              void* d_out, int out_size) {
    const float* x   = (const float*)d_in[0];
    const float* cs  = (const float*)d_in[1];
    const float* sn  = (const float*)d_in[2];
    const float* wq  = (const float*)d_in[3];
    const float* wk  = (const float*)d_in[4];
    const float* wv  = (const float*)d_in[5];
    const float* wo  = (const float*)d_in[6];
    const float* wfc = (const float*)d_in[7];
    const float* wpr = (const float*)d_in[8];
    const float* g1  = (const float*)d_in[9];
    const float* g2  = (const float*)d_in[10];
    float* out = (float*)d_out;

    float *h, *q, *k, *v, *y, *x2, *ff;
    cudaGetSymbolAddress((void**)&h,  g_h);
    cudaGetSymbolAddress((void**)&q,  g_q);
    cudaGetSymbolAddress((void**)&k,  g_k);
    cudaGetSymbolAddress((void**)&v,  g_v);
    cudaGetSymbolAddress((void**)&y,  g_y);
    cudaGetSymbolAddress((void**)&x2, g_x2);
    cudaGetSymbolAddress((void**)&ff, g_ff);

    cudaFuncSetAttribute((const void*)attn_mma,
                         cudaFuncAttributeMaxDynamicSharedMemorySize, ATTN_SMEM);
    cudaFuncSetAttribute((const void*)qkv_gemm,
                         cudaFuncAttributeMaxDynamicSharedMemorySize, GEMM_SMEM);
    cudaFuncSetAttribute((const void*)gemm_mma<0>,
                         cudaFuncAttributeMaxDynamicSharedMemorySize, GEMM_SMEM);
    cudaFuncSetAttribute((const void*)gemm_mma<1>,
                         cudaFuncAttributeMaxDynamicSharedMemorySize, GEMM_SMEM);
    cudaFuncSetAttribute((const void*)gemm_mma<2>,
                         cudaFuncAttributeMaxDynamicSharedMemorySize, GEMM_SMEM);

    // 1. h = rmsnorm(x, g1)
    rmsnorm_kernel<<<NROWS, 256>>>(x, g1, h);

    // 2+3. q,k,v = h @ {wq,wk,wv}, RoPE fused
    qkv_gemm<<<dim3(18, 32), 256, GEMM_SMEM>>>(h, wq, wk, wv, cs, sn, q, k, v);

    // 4. attention -> y
    attn_mma<<<dim3(TT / 64, HH, BB), 128, ATTN_SMEM>>>(q, k, v, y);

    // 5. x2 = x + y @ wo
    dim3 gCC(CD / 128, NROWS / 128);
    gemm_mma<1><<<gCC, 256, GEMM_SMEM>>>(y, wo, x, x2, NROWS, CD, CD);

    // 6. h = rmsnorm(x2, g2)
    rmsnorm_kernel<<<NROWS, 256>>>(x2, g2, h);

    // 7. ff = relu(h @ wfc)^2
    dim3 gFC(FFD / 128, NROWS / 128);
    gemm_mma<2><<<gFC, 256, GEMM_SMEM>>>(h, wfc, nullptr, ff, NROWS, FFD, CD);

    // 8. out = x2 + ff @ wpr
    gemm_mma<1><<<gCC, 256, GEMM_SMEM>>>(ff, wpr, x2, out, NROWS, CD, FFD);
}